// round 4
// baseline (speedup 1.0000x reference)
#include <cuda_runtime.h>

// ROI Align, NCHW in / NCHW out.
// input:  (4, 256, 200, 200) f32
// rois:   (M, 5) f32  [batch, x1, y1, x2, y2] (pre-scale coords)
// output: (M, 256, 7, 7) f32
//
// Strategy: CTA = (roi m, 32-channel block). The roi's bilinear footprint is
// <= 15x16 pixels (roi extents are 2..16 px after SPATIAL_SCALE), so we stage
// a [32ch][<=16 rows][16-col pitch] window in SMEM with coalesced row loads,
// precompute the 7 x-params and 7 y-params once, then emit 49*32 outputs with
// fully coalesced 128B stores.

#define OHW 49
static constexpr int C_ = 256;
static constexpr int H_ = 200;
static constexpr int W_ = 200;
static constexpr int CB = 32;              // channels per CTA
static constexpr int CSTRIDE = 16 * 16 + 8; // 264 floats per channel plane (+8 pad: bank stagger)

__global__ __launch_bounds__(256) void roi_align_kernel(
    const float* __restrict__ inp,
    const float* __restrict__ rois,
    float* __restrict__ out)
{
    __shared__ float tile[CB * CSTRIDE];     // ~33.8 KB
    __shared__ int   s_x0[7], s_x1[7], s_y0[7], s_y1[7];
    __shared__ float s_lx[7], s_ly[7];

    const int m   = blockIdx.x;
    const int c0  = blockIdx.y * CB;
    const int tid = threadIdx.x;

    // ---- per-roi scalars (computed redundantly by every thread; cheap) ----
    const float* r = rois + (size_t)m * 5;
    const int   b  = (int)r[0];
    const float x1 = r[1] * 0.25f;
    const float y1 = r[2] * 0.25f;
    const float x2 = r[3] * 0.25f;
    const float y2 = r[4] * 0.25f;
    const float bw = fmaxf(x2 - x1, 1.0f) / 7.0f;
    const float bh = fmaxf(y2 - y1, 1.0f) / 7.0f;

    // Window bounds (same fp formula as per-bin coords -> consistent floors).
    const float px0 = ((x1 + 0.5f * bw) * 199.0f) / 200.0f;
    const float px6 = ((x1 + 6.5f * bw) * 199.0f) / 200.0f;
    const float py0 = ((y1 + 0.5f * bh) * 199.0f) / 200.0f;
    const float py6 = ((y1 + 6.5f * bh) * 199.0f) / 200.0f;
    int xlo = (int)floorf(px0); xlo = max(0, min(xlo, W_ - 1));
    int ylo = (int)floorf(py0); ylo = max(0, min(ylo, H_ - 1));
    int xhi = (int)floorf(px6) + 1; xhi = max(xlo, min(xhi, W_ - 1));
    int yhi = (int)floorf(py6) + 1; yhi = max(ylo, min(yhi, H_ - 1));
    const int ww = min(xhi - xlo + 1, 16);
    const int wh = min(yhi - ylo + 1, 16);

    // ---- per-bin params into SMEM (threads 0..13) ----
    if (tid < 7) {
        const float px = ((x1 + ((float)tid + 0.5f) * bw) * 199.0f) / 200.0f;
        const int   x0 = (int)floorf(px);
        s_lx[tid] = px - (float)x0;
        const int xr = max(0, min(x0 - xlo, ww - 1));
        s_x0[tid] = xr;
        s_x1[tid] = min(xr + 1, ww - 1);
    } else if (tid < 14) {
        const int   t  = tid - 7;
        const float py = ((y1 + ((float)t + 0.5f) * bh) * 199.0f) / 200.0f;
        const int   y0 = (int)floorf(py);
        s_ly[t] = py - (float)y0;
        const int yr = max(0, min(y0 - ylo, wh - 1));
        s_y0[t] = yr * 16;
        s_y1[t] = min(yr + 1, wh - 1) * 16;
    }

    // ---- stage window into SMEM: warp handles channels wid, wid+8, ... ;
    //      lanes cover 2 rows x 16 cols per iteration (coalesced) ----
    const int wid  = tid >> 5;
    const int lane = tid & 31;
    const int xl   = lane & 15;
    const int ylp  = lane >> 4;
    const float* base = inp + ((size_t)b * C_ + c0) * (size_t)(H_ * W_);
    if (xl < ww) {
        for (int c = wid; c < CB; c += 8) {
            const float* bp = base + (size_t)c * (H_ * W_) + (size_t)ylo * W_ + xlo;
            float* tp = tile + c * CSTRIDE;
            for (int y = ylp; y < wh; y += 2)
                tp[y * 16 + xl] = bp[y * W_ + xl];
        }
    }
    __syncthreads();

    // ---- compute 49 bins x 32 channels; stores are fully contiguous ----
    const size_t outbase = ((size_t)m * C_ + c0) * OHW;
    #pragma unroll 4
    for (int i = tid; i < CB * OHW; i += 256) {
        const int c   = i / OHW;
        const int bin = i - c * OHW;
        const int ph  = bin / 7;
        const int pw  = bin - ph * 7;
        const float* tp = tile + c * CSTRIDE;
        const int   xr = s_x0[pw], xr1 = s_x1[pw];
        const float lx = s_lx[pw];
        const int   yo = s_y0[ph], yo1 = s_y1[ph];
        const float ly = s_ly[ph];
        const float v00 = tp[yo  + xr];
        const float v01 = tp[yo  + xr1];
        const float v10 = tp[yo1 + xr];
        const float v11 = tp[yo1 + xr1];
        const float hx = 1.0f - lx, hy = 1.0f - ly;
        out[outbase + i] = (hy * hx) * v00 + (hy * lx) * v01
                         + (ly * hx) * v10 + (ly * lx) * v11;
    }
}

extern "C" void kernel_launch(void* const* d_in, const int* in_sizes, int n_in,
                              void* d_out, int out_size)
{
    const float* inp  = (const float*)d_in[0];
    const float* rois = (const float*)d_in[1];
    float*       out  = (float*)d_out;
    const int M = in_sizes[1] / 5;          // 1024
    dim3 grid(M, C_ / CB);                  // (1024, 8)
    roi_align_kernel<<<grid, 256>>>(inp, rois, out);
}

// round 6
// speedup vs baseline: 1.8819x; 1.8819x over previous
#include <cuda_runtime.h>
#include <cstdint>

// ROI Align, NCHW in / NCHW out.  input (4,256,200,200) f32, rois (1024,5), out (1024,256,7,7).
// R5: cp.async.cg float4 staging (bypass L1), fixed-bin compute mapping (no div/mod
// in hot loop), streaming stores.

#define OHW 49
static constexpr int C_ = 256;
static constexpr int H_ = 200;
static constexpr int W_ = 200;
static constexpr int CB = 32;            // channels per CTA
static constexpr int P_  = 20;           // SMEM row pitch (floats) = 5 float4 quads
static constexpr int CSTR = 16 * P_ + 4; // 324 floats/channel (16B-aligned, bank shift 4)

__device__ __forceinline__ void cp_async16(uint32_t s_dst, const void* g_src) {
    asm volatile("cp.async.cg.shared.global [%0], [%1], 16;" :: "r"(s_dst), "l"(g_src));
}

__global__ __launch_bounds__(256) void roi_align_kernel(
    const float* __restrict__ inp,
    const float* __restrict__ rois,
    float* __restrict__ out)
{
    __shared__ float tile[CB * CSTR];    // 41472 B
    __shared__ float s_lx[7], s_ly[7];
    __shared__ int   s_xr[7], s_yo[7];

    const int m   = blockIdx.x;
    const int c0  = blockIdx.y * CB;
    const int tid = threadIdx.x;

    // ---- per-roi scalars (every thread; cheap, no smem round-trip) ----
    const float* r = rois + (size_t)m * 5;
    const int   b  = (int)r[0];
    const float x1 = r[1] * 0.25f;
    const float y1 = r[2] * 0.25f;
    const float bw = fmaxf(r[3] * 0.25f - x1, 1.0f) * (1.0f / 7.0f);
    const float bh = fmaxf(r[4] * 0.25f - y1, 1.0f) * (1.0f / 7.0f);

    const float px0 = ((x1 + 0.5f * bw) * 199.0f) / 200.0f;
    const float px6 = ((x1 + 6.5f * bw) * 199.0f) / 200.0f;
    const float py0 = ((y1 + 0.5f * bh) * 199.0f) / 200.0f;
    const float py6 = ((y1 + 6.5f * bh) * 199.0f) / 200.0f;
    int xlo = max(0, min((int)floorf(px0), W_ - 1));
    int ylo = max(0, min((int)floorf(py0), H_ - 1));
    int xhi = max(xlo, min((int)floorf(px6) + 1, W_ - 1));
    int yhi = max(ylo, min((int)floorf(py6) + 1, H_ - 1));
    const int ww = min(xhi - xlo + 1, 16);
    const int wh = min(yhi - ylo + 1, 16);
    const int ax = min(xlo & ~3, W_ - P_);                 // aligned window start (<=180)
    const int nq = min(5, (xlo - ax + ww + 3) >> 2);       // float4 quads per row

    // ---- per-bin params (threads 0..13), disjoint from staging smem ----
    if (tid < 7) {
        const float px = ((x1 + ((float)tid + 0.5f) * bw) * 199.0f) / 200.0f;
        const int   x0 = (int)floorf(px);
        s_lx[tid] = px - (float)x0;
        s_xr[tid] = max(0, min(x0 - ax, P_ - 2));          // x0+1 <= 199 always in-window
    } else if (tid < 14) {
        const int   t  = tid - 7;
        const float py = ((y1 + ((float)t + 0.5f) * bh) * 199.0f) / 200.0f;
        const int   y0 = (int)floorf(py);
        s_ly[t] = py - (float)y0;
        s_yo[t] = max(0, min(y0 - ylo, 14)) * P_;
    }

    // ---- stage: cp.async 16B quads, L1-bypass. lane -> (row rrow, quad rq) ----
    const int wid  = tid >> 5;
    const int lane = tid & 31;
    const int rrow = lane / 5;           // 0..6 (lanes 30,31 idle)
    const int rq   = lane - rrow * 5;    // 0..4
    const bool act = (lane < 30) && (rq < nq);
    const float* base = inp + ((size_t)b * C_ + c0) * (size_t)(H_ * W_)
                            + (size_t)ylo * W_ + ax;
    for (int c = wid; c < CB; c += 8) {
        const float* gp = base + (size_t)c * (H_ * W_);
        uint32_t sp = (uint32_t)__cvta_generic_to_shared(tile + c * CSTR);
        if (act) {
            for (int y = rrow; y < wh; y += 6)
                cp_async16(sp + (uint32_t)(y * P_ + rq * 4) * 4u, gp + y * W_ + rq * 4);
        }
    }
    asm volatile("cp.async.commit_group;" ::: "memory");
    asm volatile("cp.async.wait_group 0;" ::: "memory");
    __syncthreads();

    // ---- compute: thread owns a fixed bin; loop over channels (stride 5) ----
    if (tid < 5 * OHW) {                         // 245 active threads
        const int cstart = tid / OHW;            // 0..4 (once)
        const int bin    = tid - cstart * OHW;   // 0..48
        const int ph     = bin / 7;
        const int pw     = bin - ph * 7;
        const float lx = s_lx[pw], ly = s_ly[ph];
        const float hx = 1.0f - lx, hy = 1.0f - ly;
        const float w00 = hy * hx, w01 = hy * lx, w10 = ly * hx, w11 = ly * lx;
        const float* tp = tile + cstart * CSTR + s_yo[ph] + s_xr[pw];
        float* op = out + ((size_t)m * C_ + c0 + cstart) * OHW + bin;
        #pragma unroll 7
        for (int c = cstart; c < CB; c += 5, tp += 5 * CSTR, op += 5 * OHW) {
            const float v = w00 * tp[0] + w01 * tp[1]
                          + w10 * tp[P_] + w11 * tp[P_ + 1];
            __stcs(op, v);                       // streaming: keep L2 for input
        }
    }
}

extern "C" void kernel_launch(void* const* d_in, const int* in_sizes, int n_in,
                              void* d_out, int out_size)
{
    const float* inp  = (const float*)d_in[0];
    const float* rois = (const float*)d_in[1];
    float*       out  = (float*)d_out;
    const int M = in_sizes[1] / 5;               // 1024
    dim3 grid(M, C_ / CB);                       // (1024, 8)
    roi_align_kernel<<<grid, 256>>>(inp, rois, out);
}